// round 15
// baseline (speedup 1.0000x reference)
#include <cuda_runtime.h>
#include <cstdint>

#define NPTS 8192
#define DIM  256           // elements per row (256 int8 bytes)
#define KNN  11
#define NTHREADS 512
#define PAB  272           // smem pitch in BYTES (256 + 16)
#define BIGF 1e30f

// smem byte offsets
#define SMB_A   0
#define TILE_B  (128 * PAB)            // 34816 bytes per tile buffer
#define SMB_B   TILE_B                 // two B buffers follow A
#define SM_TOTAL (TILE_B * 3 + 128)    // 104576 B

__device__ __align__(16) char g_xq[(size_t)NPTS * DIM];
__device__ float g_sq[NPTS];
__device__ float g_inv[NPTS];
__device__ __align__(16) float g_meta[2 * NPTS];   // (sq, inv) per column
__device__ float g_colpart[128 * DIM];
__device__ int   g_lockv[NPTS];
__device__ float g_thresh[NPTS];
__device__ float g_heapg[(size_t)NPTS * 12];
__device__ float g_rsumg[NPTS];
__device__ float g_disc[64];

__device__ __forceinline__ uint32_t smem_u32(const void* p) {
    uint32_t a;
    asm("{ .reg .u64 t; cvta.to.shared.u64 t, %1; cvt.u32.u64 %0, t; }"
        : "=r"(a) : "l"(p));
    return a;
}
__device__ __forceinline__ void cpasync16(uint32_t dst, const void* src) {
    asm volatile("cp.async.cg.shared.global [%0], [%1], 16;"
                 :: "r"(dst), "l"(src) : "memory");
}
#define CP_COMMIT() asm volatile("cp.async.commit_group;" ::: "memory")
#define CP_WAIT0()  asm volatile("cp.async.wait_group 0;" ::: "memory")

__device__ __forceinline__ void ldsm4(uint32_t& r0, uint32_t& r1,
                                      uint32_t& r2, uint32_t& r3, uint32_t a) {
    asm volatile("ldmatrix.sync.aligned.m8n8.x4.shared.b16 {%0,%1,%2,%3}, [%4];"
                 : "=r"(r0), "=r"(r1), "=r"(r2), "=r"(r3) : "r"(a));
}
__device__ __forceinline__ void mma_s8(int* d, const uint32_t* a,
                                       const uint32_t* b) {
    asm volatile(
        "mma.sync.aligned.m16n8k32.row.col.s32.s8.s8.s32 "
        "{%0,%1,%2,%3}, {%4,%5,%6,%7}, {%8,%9}, {%0,%1,%2,%3};"
        : "+r"(d[0]), "+r"(d[1]), "+r"(d[2]), "+r"(d[3])
        : "r"(a[0]), "r"(a[1]), "r"(a[2]), "r"(a[3]), "r"(b[0]), "r"(b[1]));
}

// global locked top-11 insert; returns new threshold (heap max)
__device__ __noinline__ float ginsert(int row, float d) {
    while (atomicCAS(&g_lockv[row], 0, 1) != 0) { }
    __threadfence();
    volatile float* vhp = (volatile float*)(g_heapg + (size_t)row * 12);
    float th = ((volatile float*)g_thresh)[row];
    float ret = th;
    if (d < th) {
        float mx1 = -BIGF, mx2 = -BIGF;
        int im = 0;
        #pragma unroll
        for (int t = 0; t < KNN; t++) {
            float v = vhp[t];
            if (v > mx1) { mx2 = mx1; mx1 = v; im = t; }
            else mx2 = fmaxf(mx2, v);
        }
        vhp[im] = d;
        ret = fmaxf(mx2, d);
        ((volatile float*)g_thresh)[row] = ret;
    }
    __threadfence();
    atomicExch(&g_lockv[row], 0);
    return ret;
}

// ---- reset global per-row state (must run every launch) ----
__global__ void tg_init_kernel() {
    int i = blockIdx.x * 256 + threadIdx.x;    // 8192 threads
    g_lockv[i] = 0;
    g_thresh[i] = BIGF;
    g_rsumg[i] = 0.f;
    #pragma unroll
    for (int t = 0; t < 12; t++) g_heapg[(size_t)i * 12 + t] = BIGF;
}

// ---- quantize rows to int8 + exact fp32 norms + per-row scale ----
__global__ void tg_quant_kernel(const float* __restrict__ x) {
    int row  = (blockIdx.x * blockDim.x + threadIdx.x) >> 5;
    int lane = threadIdx.x & 31;
    const float* r = x + (size_t)row * DIM + lane * 8;
    float4 v0 = *(const float4*)(r);
    float4 v1 = *(const float4*)(r + 4);
    float sq = v0.x * v0.x + v0.y * v0.y + v0.z * v0.z + v0.w * v0.w +
               v1.x * v1.x + v1.y * v1.y + v1.z * v1.z + v1.w * v1.w;
    float am = fmaxf(fmaxf(fmaxf(fabsf(v0.x), fabsf(v0.y)),
                           fmaxf(fabsf(v0.z), fabsf(v0.w))),
                     fmaxf(fmaxf(fabsf(v1.x), fabsf(v1.y)),
                           fmaxf(fabsf(v1.z), fabsf(v1.w))));
    #pragma unroll
    for (int o = 16; o; o >>= 1) {
        sq += __shfl_xor_sync(0xffffffffu, sq, o);
        am = fmaxf(am, __shfl_xor_sync(0xffffffffu, am, o));
    }
    float s = 127.f / am;
    int q[8];
    q[0] = __float2int_rn(v0.x * s); q[1] = __float2int_rn(v0.y * s);
    q[2] = __float2int_rn(v0.z * s); q[3] = __float2int_rn(v0.w * s);
    q[4] = __float2int_rn(v1.x * s); q[5] = __float2int_rn(v1.y * s);
    q[6] = __float2int_rn(v1.z * s); q[7] = __float2int_rn(v1.w * s);
    uint32_t p0 = (q[0] & 255) | ((q[1] & 255) << 8) |
                  ((q[2] & 255) << 16) | ((uint32_t)(q[3] & 255) << 24);
    uint32_t p1 = (q[4] & 255) | ((q[5] & 255) << 8) |
                  ((q[6] & 255) << 16) | ((uint32_t)(q[7] & 255) << 24);
    ((uint2*)(g_xq + (size_t)row * DIM))[lane] = make_uint2(p0, p1);
    if (lane == 0) {
        float inv = am * (1.f / 127.f);
        g_sq[row]  = sq;
        g_inv[row] = inv;
        g_meta[2 * row]     = sq;
        g_meta[2 * row + 1] = inv;
    }
}

// ---- GDDM column sums ----
__global__ void tg_coldiff_kernel(const float* __restrict__ src,
                                  const float* __restrict__ tgt) {
    int d = threadIdx.x;
    int b = blockIdx.x;
    int r0 = b * (NPTS / 128);
    float s = 0.f;
    for (int r = 0; r < NPTS / 128; r++) {
        size_t idx = (size_t)(r0 + r) * DIM + d;
        s += src[idx] - tgt[idx];
    }
    g_colpart[b * DIM + d] = s;
}

// ---- main: symmetric (upper-triangle) int8 IMMA Gram ----
__global__ void __launch_bounds__(NTHREADS, 1)
tg_main_kernel()
{
    extern __shared__ char sm[];
    const uint32_t smb = smem_u32(sm);

    const int tid  = threadIdx.x;
    const int lane = tid & 31;
    const int warp = tid >> 5;
    const int wr   = warp >> 2;          // 0..3: 32-row group
    const int wc   = warp & 3;           // 0..3: 32-col group
    const int qid  = lane >> 2;          // 0..7
    const int qt   = lane & 3;           // 0..3

    // tile assignment: pair (p, 63-p), 65 tiles, 4 CTAs per pair
    const int p = blockIdx.x >> 2;
    const int q = blockIdx.x & 3;
    const int start = q * 16;
    const int count = (q == 3) ? 17 : 16;
    const int nA = 64 - p;

    // ldmatrix per-lane address offsets
    const int lr8 = lane & 7;
    const int a_m  = ((lane >> 3) & 1) * 8 + lr8;
    const int a_kb = (lane >> 4) * 16;
    uint32_t aaddr[2];
    #pragma unroll
    for (int mi = 0; mi < 2; mi++)
        aaddr[mi] = smb + SMB_A +
                    (uint32_t)((wr * 32 + mi * 16 + a_m) * PAB) + a_kb;
    const int b_n  = ((lane >> 4) & 1) * 8 + lr8;
    const int b_kb = ((lane >> 3) & 1) * 16;
    uint32_t baddr0[2];
    #pragma unroll
    for (int g = 0; g < 2; g++)
        baddr0[g] = smb + SMB_B +
                    (uint32_t)((wc * 32 + g * 16 + b_n) * PAB) + b_kb;

    for (int run = 0; run < 2; run++) {
        int bi, j0, j1;
        if (run == 0) {
            int t0 = start, t1 = min(start + count, nA);
            if (t0 >= t1) continue;
            bi = p; j0 = p + t0; j1 = p + t1;
        } else {
            int t0 = max(start, nA), t1 = start + count;
            if (t0 >= t1) continue;
            bi = 63 - p; j0 = bi + (t0 - nA); j1 = bi + (t1 - nA);
        }
        const int rowbase = bi * 128;

        __syncthreads();      // prior run's smem reads done
        // stage A rows + B tile j0
        {
            const char* Ag = g_xq + (size_t)rowbase * DIM;
            const char* Bg = g_xq + (size_t)j0 * 128 * DIM;
            #pragma unroll
            for (int pp = 0; pp < 4; pp++) {
                int idx = tid + pp * NTHREADS;
                int r = idx >> 4, f = idx & 15;
                cpasync16(smb + SMB_A + r * PAB + f * 16, Ag + r * DIM + f * 16);
                cpasync16(smb + SMB_B + r * PAB + f * 16, Bg + r * DIM + f * 16);
            }
            CP_COMMIT();
        }

        int rowg[4];
        float sa[4], pinv[4], rs4[4], cR[4];
        #pragma unroll
        for (int s = 0; s < 4; s++) {
            rowg[s] = rowbase + wr * 32 + s * 8 + qid;
            sa[s]   = g_sq[rowg[s]];
            pinv[s] = -2.f * g_inv[rowg[s]];
            rs4[s]  = 0.f;
            cR[s]   = BIGF;
        }

        CP_WAIT0();
        __syncthreads();

        for (int j = j0; j < j1; j++) {
            if (j + 1 < j1) {
                const char* Bg = g_xq + (size_t)(j + 1) * 128 * DIM;
                uint32_t dst = smb + SMB_B + ((j + 1 - j0) & 1) * TILE_B;
                #pragma unroll
                for (int pp = 0; pp < 4; pp++) {
                    int idx = tid + pp * NTHREADS;
                    int r = idx >> 4, f = idx & 15;
                    cpasync16(dst + r * PAB + f * 16, Bg + r * DIM + f * 16);
                }
                CP_COMMIT();
            }

            const uint32_t bofs = ((j - j0) & 1) * TILE_B;

            int acc[2][4][4];
            #pragma unroll
            for (int mi = 0; mi < 2; mi++)
                #pragma unroll
                for (int ni = 0; ni < 4; ni++)
                    #pragma unroll
                    for (int jj = 0; jj < 4; jj++) acc[mi][ni][jj] = 0;

            #pragma unroll
            for (int kk = 0; kk < 8; kk++) {
                const uint32_t kby = kk * 32;
                uint32_t af[2][4], bf[2][4];
                ldsm4(af[0][0], af[0][1], af[0][2], af[0][3], aaddr[0] + kby);
                ldsm4(af[1][0], af[1][1], af[1][2], af[1][3], aaddr[1] + kby);
                ldsm4(bf[0][0], bf[0][1], bf[0][2], bf[0][3],
                      baddr0[0] + bofs + kby);
                ldsm4(bf[1][0], bf[1][1], bf[1][2], bf[1][3],
                      baddr0[1] + bofs + kby);
                #pragma unroll
                for (int mi = 0; mi < 2; mi++)
                    #pragma unroll
                    for (int g = 0; g < 2; g++) {
                        mma_s8(acc[mi][2 * g + 0], af[mi], &bf[g][0]);
                        mma_s8(acc[mi][2 * g + 1], af[mi], &bf[g][2]);
                    }
            }

            // epilogue: distances; row-side always, col-side when off-diagonal
            const int colbase = j * 128;
            const bool diag = (j == bi);

            #pragma unroll
            for (int s = 0; s < 4; s++)
                cR[s] = fminf(cR[s], __ldg(&g_thresh[rowg[s]]));
            float cC[8], cs[8];
            #pragma unroll
            for (int k2 = 0; k2 < 8; k2++) {
                cC[k2] = __ldg(&g_thresh[colbase + wc * 32 +
                                         (k2 >> 1) * 8 + 2 * qt + (k2 & 1)]);
                cs[k2] = 0.f;
            }

            #pragma unroll
            for (int ni = 0; ni < 4; ni++) {
                const float4 mt = __ldg((const float4*)
                    (g_meta + 2 * (colbase + wc * 32 + ni * 8 + 2 * qt)));
                const int cg0 = colbase + wc * 32 + ni * 8 + 2 * qt;
                #pragma unroll
                for (int mi = 0; mi < 2; mi++)
                    #pragma unroll
                    for (int hf = 0; hf < 2; hf++) {
                        const int s = mi * 2 + hf;
                        float f0 = __int2float_rn(acc[mi][ni][hf * 2 + 0]);
                        float f1 = __int2float_rn(acc[mi][ni][hf * 2 + 1]);
                        float d2a = fmaf(f0, mt.y * pinv[s], sa[s] + mt.x);
                        float d2b = fmaf(f1, mt.w * pinv[s], sa[s] + mt.z);
                        d2a = fmaxf(d2a, 1e-12f);
                        d2b = fmaxf(d2b, 1e-12f);
                        float da = d2a * rsqrtf(d2a);
                        float db = d2b * rsqrtf(d2b);
                        rs4[s] += da + db;
                        if (da < cR[s]) cR[s] = ginsert(rowg[s], da);
                        if (db < cR[s]) cR[s] = ginsert(rowg[s], db);
                        if (!diag) {
                            cs[ni * 2 + 0] += da;
                            cs[ni * 2 + 1] += db;
                            if (da < cC[ni * 2 + 0])
                                cC[ni * 2 + 0] = ginsert(cg0, da);
                            if (db < cC[ni * 2 + 1])
                                cC[ni * 2 + 1] = ginsert(cg0 + 1, db);
                        }
                    }
            }

            if (!diag) {
                #pragma unroll
                for (int k2 = 0; k2 < 8; k2++) {
                    float v = cs[k2];
                    v += __shfl_xor_sync(0xffffffffu, v, 4);
                    v += __shfl_xor_sync(0xffffffffu, v, 8);
                    v += __shfl_xor_sync(0xffffffffu, v, 16);
                    if (qid == 0)
                        atomicAdd(&g_rsumg[colbase + wc * 32 +
                                           (k2 >> 1) * 8 + 2 * qt + (k2 & 1)], v);
                }
            }

            CP_WAIT0();
            __syncthreads();   // next B tile staged; cur buf reads done
        }

        // run end: dump row-side sums
        #pragma unroll
        for (int s = 0; s < 4; s++) {
            float v = rs4[s];
            v += __shfl_xor_sync(0xffffffffu, v, 1);
            v += __shfl_xor_sync(0xffffffffu, v, 2);
            if (qt == 0) atomicAdd(&g_rsumg[rowg[s]], v);
        }
    }
}

// ---- TSDM head from global heaps ----
__global__ void tg_merge_kernel(const float* __restrict__ w_tsdm,
                                const float* __restrict__ b_tsdm)
{
    __shared__ float buf[128];
    int row = blockIdx.x * 128 + threadIdx.x;
    float s11 = 0.f, mn = BIGF;
    #pragma unroll
    for (int t = 0; t < KNN; t++) {
        float v = g_heapg[(size_t)row * 12 + t];
        s11 += v;
        mn = fminf(mn, v);
    }
    float sep = g_rsumg[row] * (1.f / (float)(NPTS - 1));
    float comp = (s11 - mn) * 0.1f;
    float disc = fabsf(comp * w_tsdm[0] + sep * w_tsdm[1] + b_tsdm[0]);
    buf[threadIdx.x] = disc;
    __syncthreads();
    int lane = threadIdx.x & 31, w = threadIdx.x >> 5;
    float v = buf[threadIdx.x];
    #pragma unroll
    for (int o = 16; o; o >>= 1) v += __shfl_xor_sync(0xffffffffu, v, o);
    if (lane == 0) buf[w] = v;
    __syncthreads();
    if (threadIdx.x == 0)
        g_disc[blockIdx.x] = buf[0] + buf[1] + buf[2] + buf[3];
}

// ---- final: GDDM head + disc mean (parallel reductions) ----
__global__ void tg_final_kernel(const float* __restrict__ w_gddm,
                                const float* __restrict__ b_gddm,
                                float* __restrict__ out)
{
    __shared__ float red[16];
    int d = threadIdx.x;           // 256
    int lane = d & 31, w = d >> 5;
    float s = 0.f;
    #pragma unroll 8
    for (int b = 0; b < 128; b++) s += g_colpart[b * DIM + d];
    float v = (s * (1.f / (float)NPTS)) * w_gddm[d];
    #pragma unroll
    for (int o = 16; o; o >>= 1) v += __shfl_xor_sync(0xffffffffu, v, o);
    if (lane == 0) red[w] = v;
    float dsc = (d < 64) ? g_disc[d] : 0.f;
    #pragma unroll
    for (int o = 16; o; o >>= 1) dsc += __shfl_xor_sync(0xffffffffu, dsc, o);
    if (lane == 0 && w < 2) red[8 + w] = dsc;
    __syncthreads();
    if (d == 0) {
        float t = 0.f;
        #pragma unroll
        for (int i = 0; i < 8; i++) t += red[i];
        out[0] = fabsf(t + b_gddm[0]);
        out[1] = (red[8] + red[9]) * (1.f / (float)NPTS);
    }
}

extern "C" void kernel_launch(void* const* d_in, const int* in_sizes, int n_in,
                              void* d_out, int out_size) {
    const float* src    = (const float*)d_in[0];
    const float* tgt    = (const float*)d_in[1];
    const float* w_tsdm = (const float*)d_in[2];
    const float* b_tsdm = (const float*)d_in[3];
    const float* w_gddm = (const float*)d_in[4];
    const float* b_gddm = (const float*)d_in[5];
    float* out = (float*)d_out;

    cudaFuncSetAttribute(tg_main_kernel,
                         cudaFuncAttributeMaxDynamicSharedMemorySize, SM_TOTAL);

    tg_init_kernel<<<32, 256>>>();
    tg_quant_kernel<<<NPTS / 8, 256>>>(tgt);
    tg_coldiff_kernel<<<128, DIM>>>(src, tgt);
    tg_main_kernel<<<128, NTHREADS, SM_TOTAL>>>();
    tg_merge_kernel<<<NPTS / 128, 128>>>(w_tsdm, b_tsdm);
    tg_final_kernel<<<1, DIM>>>(w_gddm, b_gddm, out);
}

// round 17
// speedup vs baseline: 8.9091x; 8.9091x over previous
#include <cuda_runtime.h>
#include <cstdint>

#define NPTS 8192
#define DIM  256           // elements per row (256 int8 bytes)
#define KNN  11
#define NTHREADS 512
#define PAB  272           // int8 smem pitch in BYTES (256 + 16)
#define BIGF 1e30f
#define QS   1024.0f       // distance fixed-point scale

// smem byte offsets (pass 1)
#define SMB_A   0
#define TILE_SZ (128 * PAB)             // 34816
#define SMB_B   TILE_SZ
#define SPITCH  272                     // u16 stage pitch in bytes (16*17)
#define STG_SZ  (128 * SPITCH)          // 34816
#define SMB_SD  (TILE_SZ * 2)
#define SMB_ST  (SMB_SD + STG_SZ)
#define SM_TOTAL (SMB_ST + STG_SZ)      // 139264 B

__device__ __align__(16) char g_xq[(size_t)NPTS * DIM];
__device__ float g_sq[NPTS];
__device__ float g_inv[NPTS];
__device__ __align__(16) float g_meta[2 * NPTS];
__device__ float g_colpart[128 * DIM];
__device__ __align__(16) uint16_t g_D[(size_t)NPTS * NPTS];   // 134 MB scratch
__device__ float g_discrow[NPTS];

__device__ __forceinline__ uint32_t smem_u32(const void* p) {
    uint32_t a;
    asm("{ .reg .u64 t; cvta.to.shared.u64 t, %1; cvt.u32.u64 %0, t; }"
        : "=r"(a) : "l"(p));
    return a;
}
__device__ __forceinline__ void cpasync16(uint32_t dst, const void* src) {
    asm volatile("cp.async.cg.shared.global [%0], [%1], 16;"
                 :: "r"(dst), "l"(src) : "memory");
}
#define CP_COMMIT() asm volatile("cp.async.commit_group;" ::: "memory")
#define CP_WAIT0()  asm volatile("cp.async.wait_group 0;" ::: "memory")

__device__ __forceinline__ void ldsm4(uint32_t& r0, uint32_t& r1,
                                      uint32_t& r2, uint32_t& r3, uint32_t a) {
    asm volatile("ldmatrix.sync.aligned.m8n8.x4.shared.b16 {%0,%1,%2,%3}, [%4];"
                 : "=r"(r0), "=r"(r1), "=r"(r2), "=r"(r3) : "r"(a));
}
__device__ __forceinline__ void mma_s8(int* d, const uint32_t* a,
                                       const uint32_t* b) {
    asm volatile(
        "mma.sync.aligned.m16n8k32.row.col.s32.s8.s8.s32 "
        "{%0,%1,%2,%3}, {%4,%5,%6,%7}, {%8,%9}, {%0,%1,%2,%3};"
        : "+r"(d[0]), "+r"(d[1]), "+r"(d[2]), "+r"(d[3])
        : "r"(a[0]), "r"(a[1]), "r"(a[2]), "r"(a[3]), "r"(b[0]), "r"(b[1]));
}

// ascending sorted 11-array insert, unsigned (caller checked v < hh[10])
__device__ __forceinline__ void ins11u(unsigned* hh, unsigned v) {
    hh[10] = v;
    #pragma unroll
    for (int t = 10; t > 0; t--) {
        unsigned lo = umin(hh[t - 1], hh[t]);
        unsigned hi = umax(hh[t - 1], hh[t]);
        hh[t - 1] = lo; hh[t] = hi;
    }
}

// triangle tile id -> (i, j), i <= j, 64x64 blocks; S(i) = i*64 - i(i-1)/2
__device__ __forceinline__ int2 tile_ij(int t) {
    int i = (int)(64.5f - sqrtf(64.5f * 64.5f - 2.0f * (float)t));
    i = max(0, min(63, i));
    while (i < 63 && (i + 1) * 64 - ((i + 1) * i) / 2 <= t) i++;
    while (i > 0 && i * 64 - (i * (i - 1)) / 2 > t) i--;
    int j = i + (t - (i * 64 - (i * (i - 1)) / 2));
    return make_int2(i, j);
}

// ---- quantize rows to int8 + exact fp32 norms + per-row scale ----
__global__ void tg_quant_kernel(const float* __restrict__ x) {
    int row  = (blockIdx.x * blockDim.x + threadIdx.x) >> 5;
    int lane = threadIdx.x & 31;
    const float* r = x + (size_t)row * DIM + lane * 8;
    float4 v0 = *(const float4*)(r);
    float4 v1 = *(const float4*)(r + 4);
    float sq = v0.x * v0.x + v0.y * v0.y + v0.z * v0.z + v0.w * v0.w +
               v1.x * v1.x + v1.y * v1.y + v1.z * v1.z + v1.w * v1.w;
    float am = fmaxf(fmaxf(fmaxf(fabsf(v0.x), fabsf(v0.y)),
                           fmaxf(fabsf(v0.z), fabsf(v0.w))),
                     fmaxf(fmaxf(fabsf(v1.x), fabsf(v1.y)),
                           fmaxf(fabsf(v1.z), fabsf(v1.w))));
    #pragma unroll
    for (int o = 16; o; o >>= 1) {
        sq += __shfl_xor_sync(0xffffffffu, sq, o);
        am = fmaxf(am, __shfl_xor_sync(0xffffffffu, am, o));
    }
    float s = 127.f / am;
    int q[8];
    q[0] = __float2int_rn(v0.x * s); q[1] = __float2int_rn(v0.y * s);
    q[2] = __float2int_rn(v0.z * s); q[3] = __float2int_rn(v0.w * s);
    q[4] = __float2int_rn(v1.x * s); q[5] = __float2int_rn(v1.y * s);
    q[6] = __float2int_rn(v1.z * s); q[7] = __float2int_rn(v1.w * s);
    uint32_t p0 = (q[0] & 255) | ((q[1] & 255) << 8) |
                  ((q[2] & 255) << 16) | ((uint32_t)(q[3] & 255) << 24);
    uint32_t p1 = (q[4] & 255) | ((q[5] & 255) << 8) |
                  ((q[6] & 255) << 16) | ((uint32_t)(q[7] & 255) << 24);
    ((uint2*)(g_xq + (size_t)row * DIM))[lane] = make_uint2(p0, p1);
    if (lane == 0) {
        float inv = am * (1.f / 127.f);
        g_sq[row]  = sq;
        g_inv[row] = inv;
        g_meta[2 * row]     = sq;
        g_meta[2 * row + 1] = inv;
    }
}

// ---- GDDM column sums ----
__global__ void tg_coldiff_kernel(const float* __restrict__ src,
                                  const float* __restrict__ tgt) {
    int d = threadIdx.x;
    int b = blockIdx.x;
    int r0 = b * (NPTS / 128);
    float s = 0.f;
    for (int r = 0; r < NPTS / 128; r++) {
        size_t idx = (size_t)(r0 + r) * DIM + d;
        s += src[idx] - tgt[idx];
    }
    g_colpart[b * DIM + d] = s;
}

// stage one 128-row int8 block into smem at byte offset `off`
#define STAGE_BLK(off, blk) do {                                              \
    const char* G_ = g_xq + (size_t)(blk) * 128 * DIM;                        \
    _Pragma("unroll")                                                         \
    for (int pp_ = 0; pp_ < 4; pp_++) {                                       \
        int idx_ = tid + pp_ * NTHREADS;                                      \
        int r_ = idx_ >> 4, f_ = idx_ & 15;                                   \
        cpasync16(smb + (off) + r_ * PAB + f_ * 16, G_ + r_ * DIM + f_ * 16); \
    }                                                                         \
} while (0)

// ---- pass 1: symmetric int8 IMMA Gram -> u16 distance matrix ----
__global__ void __launch_bounds__(NTHREADS, 1)
tg_gemm_kernel()
{
    extern __shared__ char sm[];
    const uint32_t smb = smem_u32(sm);

    const int tid  = threadIdx.x;
    const int lane = tid & 31;
    const int warp = tid >> 5;
    const int wr   = warp >> 2;          // 0..3: 32-row group
    const int wc   = warp & 3;           // 0..3: 32-col group
    const int qid  = lane >> 2;          // 0..7
    const int qt   = lane & 3;           // 0..3

    // ldmatrix per-lane addresses
    const int lr8 = lane & 7;
    const int a_m  = ((lane >> 3) & 1) * 8 + lr8;
    const int a_kb = (lane >> 4) * 16;
    uint32_t aaddr[2];
    #pragma unroll
    for (int mi = 0; mi < 2; mi++)
        aaddr[mi] = smb + SMB_A +
                    (uint32_t)((wr * 32 + mi * 16 + a_m) * PAB) + a_kb;
    const int b_n  = ((lane >> 4) & 1) * 8 + lr8;
    const int b_kb = ((lane >> 3) & 1) * 16;
    uint32_t baddr[2];
    #pragma unroll
    for (int g = 0; g < 2; g++)
        baddr[g] = smb + SMB_B +
                   (uint32_t)((wc * 32 + g * 16 + b_n) * PAB) + b_kb;

    int t = blockIdx.x * 16;
    int2 ij = tile_ij(t);
    STAGE_BLK(SMB_A, ij.x);
    STAGE_BLK(SMB_B, ij.y);
    CP_COMMIT();

    for (int m = 0; m < 16; m++, t++) {
        const int bi = ij.x, bj = ij.y;
        const int rowbase = bi * 128;
        const int colbase = bj * 128;

        CP_WAIT0();
        __syncthreads();

        float sa[4], pinv[4];
        #pragma unroll
        for (int s = 0; s < 4; s++) {
            int rg = rowbase + wr * 32 + s * 8 + qid;
            sa[s]   = g_sq[rg];
            pinv[s] = -2.f * g_inv[rg];
        }

        int acc[2][4][4];
        #pragma unroll
        for (int mi = 0; mi < 2; mi++)
            #pragma unroll
            for (int ni = 0; ni < 4; ni++)
                #pragma unroll
                for (int jj = 0; jj < 4; jj++) acc[mi][ni][jj] = 0;

        #pragma unroll
        for (int kk = 0; kk < 8; kk++) {
            const uint32_t kby = kk * 32;
            uint32_t af[2][4], bf[2][4];
            ldsm4(af[0][0], af[0][1], af[0][2], af[0][3], aaddr[0] + kby);
            ldsm4(af[1][0], af[1][1], af[1][2], af[1][3], aaddr[1] + kby);
            ldsm4(bf[0][0], bf[0][1], bf[0][2], bf[0][3], baddr[0] + kby);
            ldsm4(bf[1][0], bf[1][1], bf[1][2], bf[1][3], baddr[1] + kby);
            #pragma unroll
            for (int mi = 0; mi < 2; mi++)
                #pragma unroll
                for (int g = 0; g < 2; g++) {
                    mma_s8(acc[mi][2 * g + 0], af[mi], &bf[g][0]);
                    mma_s8(acc[mi][2 * g + 1], af[mi], &bf[g][2]);
                }
        }

        __syncthreads();          // all warps done reading A/B

        if (m + 1 < 16) {         // prefetch next tile (overlaps epilogue)
            ij = tile_ij(t + 1);
            STAGE_BLK(SMB_A, ij.x);
            STAGE_BLK(SMB_B, ij.y);
            CP_COMMIT();
        }

        // epilogue: distances -> u16 -> stage direct + transpose
        #pragma unroll
        for (int ni = 0; ni < 4; ni++) {
            const float4 mt = __ldg((const float4*)
                (g_meta + 2 * (colbase + wc * 32 + ni * 8 + 2 * qt)));
            const int c0 = wc * 32 + ni * 8 + 2 * qt;   // local col (even)
            #pragma unroll
            for (int mi = 0; mi < 2; mi++)
                #pragma unroll
                for (int hf = 0; hf < 2; hf++) {
                    const int s = mi * 2 + hf;
                    const int rl = wr * 32 + s * 8 + qid;  // local row
                    float f0 = __int2float_rn(acc[mi][ni][hf * 2 + 0]);
                    float f1 = __int2float_rn(acc[mi][ni][hf * 2 + 1]);
                    float d2a = fmaf(f0, mt.y * pinv[s], sa[s] + mt.x);
                    float d2b = fmaf(f1, mt.w * pinv[s], sa[s] + mt.z);
                    d2a = fmaxf(d2a, 1e-12f);
                    d2b = fmaxf(d2b, 1e-12f);
                    float da = d2a * rsqrtf(d2a);
                    float db = d2b * rsqrtf(d2b);
                    uint32_t qa = umin(__float2uint_rn(da * QS), 65535u);
                    uint32_t qb = umin(__float2uint_rn(db * QS), 65535u);
                    *(uint32_t*)(sm + SMB_SD + rl * SPITCH + c0 * 2) =
                        qa | (qb << 16);
                    *(uint16_t*)(sm + SMB_ST + c0 * SPITCH + rl * 2) =
                        (uint16_t)qa;
                    *(uint16_t*)(sm + SMB_ST + (c0 + 1) * SPITCH + rl * 2) =
                        (uint16_t)qb;
                }
        }

        __syncthreads();          // stages complete

        // coalesced writeout: 512 threads x 64 B per block (32 KB)
        {
            const int r  = tid >> 2;       // 0..127
            const int pt = tid & 3;        // 64-byte quarter of the 256B row
            uint16_t* dst = g_D + (size_t)(rowbase + r) * NPTS +
                            colbase + pt * 32;
            const char* sp = sm + SMB_SD + r * SPITCH + pt * 64;
            #pragma unroll
            for (int i4 = 0; i4 < 4; i4++)
                ((uint4*)dst)[i4] = *(const uint4*)(sp + i4 * 16);
            if (bi != bj) {
                uint16_t* dstT = g_D + (size_t)(colbase + r) * NPTS +
                                 rowbase + pt * 32;
                const char* spT = sm + SMB_ST + r * SPITCH + pt * 64;
                #pragma unroll
                for (int i4 = 0; i4 < 4; i4++)
                    ((uint4*)dstT)[i4] = *(const uint4*)(spT + i4 * 16);
            }
        }
        // loop-top CP_WAIT0 + sync orders writeout vs next tile's stages
    }
}

// ---- pass 2: warp per row: top-11 + exact rowsum + TSDM head ----
__global__ void __launch_bounds__(256)
tg_topk_kernel(const float* __restrict__ w_tsdm,
               const float* __restrict__ b_tsdm)
{
    __shared__ uint16_t wb[8][354];
    const int tid  = threadIdx.x;
    const int lane = tid & 31;
    const int w    = tid >> 5;
    const int row  = blockIdx.x * 8 + w;

    const uint4* R4 = (const uint4*)(g_D + (size_t)row * NPTS);
    unsigned hh[11];
    #pragma unroll
    for (int t = 0; t < KNN; t++) hh[t] = 0x7FFFFFFFu;
    unsigned sum = 0;

    #pragma unroll 4
    for (int it = 0; it < 32; it++) {
        uint4 v = R4[lane + it * 32];
        unsigned a4[4] = {v.x, v.y, v.z, v.w};
        #pragma unroll
        for (int q = 0; q < 4; q++) {
            unsigned lo = a4[q] & 0xFFFFu, hi = a4[q] >> 16;
            sum += lo + hi;
            if (lo < hh[10]) ins11u(hh, lo);
            if (hi < hh[10]) ins11u(hh, hi);
        }
    }

    #pragma unroll
    for (int o = 16; o; o >>= 1) sum += __shfl_xor_sync(0xffffffffu, sum, o);

    #pragma unroll
    for (int t = 0; t < KNN; t++) wb[w][lane * 11 + t] = (uint16_t)hh[t];
    __syncwarp();

    if (lane == 0) {
        for (int c = 11; c < 352; c++) {
            unsigned v = wb[w][c];
            if (v < hh[10]) ins11u(hh, v);
        }
        float s11 = 0.f;
        #pragma unroll
        for (int t = 0; t < KNN; t++) s11 += (float)hh[t];
        s11 *= (1.f / QS);
        float mn = (float)hh[0] * (1.f / QS);
        float rowsum = (float)sum * (1.f / QS);
        float sep = rowsum * (1.f / (float)(NPTS - 1));
        float comp = (s11 - mn) * 0.1f;
        g_discrow[row] = fabsf(comp * __ldg(&w_tsdm[0]) +
                               sep * __ldg(&w_tsdm[1]) + __ldg(&b_tsdm[0]));
    }
}

// ---- final: GDDM head + disc mean (deterministic reductions) ----
__global__ void tg_final_kernel(const float* __restrict__ w_gddm,
                                const float* __restrict__ b_gddm,
                                float* __restrict__ out)
{
    __shared__ float red[16];
    int d = threadIdx.x;           // 256
    int lane = d & 31, w = d >> 5;
    float s = 0.f;
    #pragma unroll 8
    for (int b = 0; b < 128; b++) s += g_colpart[b * DIM + d];
    float v = (s * (1.f / (float)NPTS)) * w_gddm[d];
    #pragma unroll
    for (int o = 16; o; o >>= 1) v += __shfl_xor_sync(0xffffffffu, v, o);
    if (lane == 0) red[w] = v;
    float dsc = 0.f;
    #pragma unroll
    for (int k = 0; k < 32; k++) dsc += g_discrow[d + k * 256];
    #pragma unroll
    for (int o = 16; o; o >>= 1) dsc += __shfl_xor_sync(0xffffffffu, dsc, o);
    if (lane == 0) red[8 + w] = dsc;
    __syncthreads();
    if (d == 0) {
        float t = 0.f, ds = 0.f;
        #pragma unroll
        for (int i = 0; i < 8; i++) { t += red[i]; ds += red[8 + i]; }
        out[0] = fabsf(t + b_gddm[0]);
        out[1] = ds * (1.f / (float)NPTS);
    }
}

extern "C" void kernel_launch(void* const* d_in, const int* in_sizes, int n_in,
                              void* d_out, int out_size) {
    const float* src    = (const float*)d_in[0];
    const float* tgt    = (const float*)d_in[1];
    const float* w_tsdm = (const float*)d_in[2];
    const float* b_tsdm = (const float*)d_in[3];
    const float* w_gddm = (const float*)d_in[4];
    const float* b_gddm = (const float*)d_in[5];
    float* out = (float*)d_out;

    cudaFuncSetAttribute(tg_gemm_kernel,
                         cudaFuncAttributeMaxDynamicSharedMemorySize, SM_TOTAL);

    tg_quant_kernel<<<NPTS / 8, 256>>>(tgt);
    tg_coldiff_kernel<<<128, DIM>>>(src, tgt);
    tg_gemm_kernel<<<130, NTHREADS, SM_TOTAL>>>();
    tg_topk_kernel<<<NPTS / 8, 256>>>(w_tsdm, b_tsdm);
    tg_final_kernel<<<1, DIM>>>(w_gddm, b_gddm, out);
}